// round 1
// baseline (speedup 1.0000x reference)
#include <cuda_runtime.h>
#include <cuda_bf16.h>

// Conv2d: x[32,128,56,56] (f32) * w[256,128,3,3] -> out[32,256,56,56], pad=1, stride=1.
// Round 0: tiled direct conv on FP32 FMA pipe. Each block: one (n,h) row,
// 64 output channels. 256 thr = 32 co-pairs x 8 w-groups; thread = 2co x 7w.

#define C_IN   128
#define C_OUT  256
#define HH     56
#define WW     56
#define NN     32

constexpr int CI_CHUNK = 8;
constexpr int CO_TILE  = 64;
constexpr int XW       = 64;   // padded smem row width
constexpr int WSTR     = 73;   // padded per-co weight stride (8*9=72 -> 73, conflict-free)

__global__ __launch_bounds__(256, 3)
void conv3x3_kernel(const float* __restrict__ x,
                    const float* __restrict__ wgt,
                    float* __restrict__ out)
{
    __shared__ float s_x[CI_CHUNK][3][XW];
    __shared__ float s_w[CO_TILE * WSTR];

    const int tid     = threadIdx.x;
    const int n       = blockIdx.z;
    const int h       = blockIdx.y;
    const int co_base = blockIdx.x * CO_TILE;

    const int wg  = tid & 7;     // w-group 0..7
    const int cp  = tid >> 3;    // co-pair 0..31
    const int coA = cp * 2;      // local output channels
    const int coB = coA + 1;
    const int w0  = wg * 7;      // first output w for this thread

    float acc[2][7];
    #pragma unroll
    for (int a = 0; a < 2; a++)
        #pragma unroll
        for (int j = 0; j < 7; j++) acc[a][j] = 0.0f;

    for (int cc = 0; cc < C_IN / CI_CHUNK; cc++) {
        const int ci_base = cc * CI_CHUNK;

        // Stage input: 8 ci x 3 rows x 58 (w=-1..56), zero-padded edges.
        for (int i = tid; i < CI_CHUNK * 3 * 58; i += 256) {
            int ci  = i / (3 * 58);
            int rem = i - ci * (3 * 58);
            int r   = rem / 58;
            int j   = rem - r * 58;
            int gh  = h - 1 + r;
            int gw  = j - 1;
            float v = 0.0f;
            if ((unsigned)gh < (unsigned)HH && (unsigned)gw < (unsigned)WW)
                v = x[(((size_t)n * C_IN + ci_base + ci) * HH + gh) * WW + gw];
            s_x[ci][r][j] = v;
        }
        // Stage weights: s_w[co*WSTR + ci*9 + k]; 72 consecutive floats per co (coalesced).
        for (int i = tid; i < CO_TILE * 72; i += 256) {
            int co  = i / 72;
            int rem = i - co * 72;  // ci*9 + k
            s_w[co * WSTR + rem] =
                wgt[(size_t)(co_base + co) * (C_IN * 9) + (size_t)ci_base * 9 + rem];
        }
        __syncthreads();

        #pragma unroll
        for (int ci = 0; ci < CI_CHUNK; ci++) {
            float wa[9], wb[9];
            #pragma unroll
            for (int k = 0; k < 9; k++) {
                wa[k] = s_w[coA * WSTR + ci * 9 + k];
                wb[k] = s_w[coB * WSTR + ci * 9 + k];
            }
            float xr[3][9];
            #pragma unroll
            for (int r = 0; r < 3; r++)
                #pragma unroll
                for (int t = 0; t < 9; t++)
                    xr[r][t] = s_x[ci][r][w0 + t];

            #pragma unroll
            for (int j = 0; j < 7; j++)
                #pragma unroll
                for (int r = 0; r < 3; r++)
                    #pragma unroll
                    for (int c = 0; c < 3; c++) {
                        acc[0][j] = fmaf(xr[r][j + c], wa[r * 3 + c], acc[0][j]);
                        acc[1][j] = fmaf(xr[r][j + c], wb[r * 3 + c], acc[1][j]);
                    }
        }
        __syncthreads();
    }

    // Write 2 co x 7 consecutive w per thread.
    #pragma unroll
    for (int a = 0; a < 2; a++) {
        int co = co_base + (a == 0 ? coA : coB);
        float* o = out + (((size_t)n * C_OUT + co) * HH + h) * WW + w0;
        #pragma unroll
        for (int j = 0; j < 7; j++) o[j] = acc[a][j];
    }
}

extern "C" void kernel_launch(void* const* d_in, const int* in_sizes, int n_in,
                              void* d_out, int out_size)
{
    const float* x   = (const float*)d_in[0];
    const float* wgt = (const float*)d_in[1];
    float*       out = (float*)d_out;

    dim3 grid(C_OUT / CO_TILE, HH, NN);   // 4 x 56 x 32 = 7168 blocks
    conv3x3_kernel<<<grid, 256>>>(x, wgt, out);
}

// round 3
// speedup vs baseline: 4.6100x; 4.6100x over previous
#include <cuda_runtime.h>
#include <cuda.h>
#include <cuda_bf16.h>
#include <cstdint>

#define NNB 32
#define CI  128
#define CO  256
#define HH  56
#define WW  56

// Padded NHWC x: [n][59 rows][64 cols][128 ci], rows 1..56 hold h=0..55,
// cols 0..55 hold w, everything else zero. +128 front guard for the (0,0,-1) read.
__device__ float g_xt[128 + (size_t)NNB * 59 * 64 * CI];
__device__ float g_wt[9 * CO * CI];   // [tap][co][ci], tf32-rounded

// ---------------- helpers ----------------
__device__ __forceinline__ uint32_t f2tf32(float v) {
    uint32_t u;
    asm("cvt.rna.tf32.f32 %0, %1;" : "=r"(u) : "f"(v));
    return u;
}

__device__ __forceinline__ void cp_async16(void* dst_smem, const void* src) {
    uint32_t d = (uint32_t)__cvta_generic_to_shared(dst_smem);
    asm volatile("cp.async.cg.shared.global [%0], [%1], 16;" :: "r"(d), "l"(src) : "memory");
}
#define CP_COMMIT() asm volatile("cp.async.commit_group;" ::: "memory")
#define CP_WAIT1()  asm volatile("cp.async.wait_group 1;" ::: "memory")

__device__ __forceinline__ void mma_tf32(float d[4], const uint32_t a[4], const uint32_t b[2]) {
    asm volatile(
        "mma.sync.aligned.m16n8k8.row.col.f32.tf32.tf32.f32 "
        "{%0,%1,%2,%3}, {%4,%5,%6,%7}, {%8,%9}, {%0,%1,%2,%3};"
        : "+f"(d[0]), "+f"(d[1]), "+f"(d[2]), "+f"(d[3])
        : "r"(a[0]), "r"(a[1]), "r"(a[2]), "r"(a[3]), "r"(b[0]), "r"(b[1]));
}

// ---------------- prologue ----------------
__global__ void xpose_kernel(const float* __restrict__ x) {
    __shared__ float s[32][57];
    const int cib = blockIdx.x;   // ci block of 32
    const int h   = blockIdx.y;
    const int n   = blockIdx.z;
    const int tid = threadIdx.x;
    for (int idx = tid; idx < 32 * WW; idx += 256) {
        int ci = idx / WW, w = idx % WW;
        s[ci][w] = x[(((size_t)n * CI + cib * 32 + ci) * HH + h) * WW + w];
    }
    __syncthreads();
    float* xb = g_xt + 128;
    for (int idx = tid; idx < 32 * WW; idx += 256) {
        int w = idx / 32, ci = idx % 32;
        uint32_t v = f2tf32(s[ci][w]);
        xb[((size_t)(n * 59 + h + 1) * 64 + w) * CI + cib * 32 + ci] = __uint_as_float(v);
    }
}

__global__ void wxform_kernel(const float* __restrict__ wgt) {
    int idx = blockIdx.x * 256 + threadIdx.x;
    if (idx >= 9 * CO * CI) return;
    int ci  = idx % CI;
    int t   = idx / CI;
    int co  = t % CO;
    int tap = t / CO;
    g_wt[idx] = __uint_as_float(f2tf32(wgt[((size_t)co * CI + ci) * 9 + tap]));
}

// ---------------- main kernel ----------------
constexpr int STG   = 3;
constexpr int SROW  = 36;                       // padded smem row (floats)
constexpr int TILEB = 128 * SROW;               // floats per operand per stage
constexpr int SMEM_BYTES = STG * 2 * TILEB * 4; // 110592

__global__ __launch_bounds__(256, 2)
void conv_mma_kernel(float* __restrict__ out)
{
    extern __shared__ float sm[];
    float* sA = sm;                // [STG][128][36]
    float* sB = sm + STG * TILEB;

    const int tid  = threadIdx.x;
    const int lane = tid & 31;
    const int warp = tid >> 5;
    const int g    = lane >> 2;
    const int t    = lane & 3;
    const int warp_m = (warp >> 1) * 32;
    const int warp_n = (warp & 1) * 64;

    const int co_base = blockIdx.x * 128;
    const int h0      = blockIdx.y * 2;
    const int n       = blockIdx.z;

    const float* xb = g_xt + 128;

    float acc[2][8][4];
    #pragma unroll
    for (int mi = 0; mi < 2; mi++)
        #pragma unroll
        for (int ni = 0; ni < 8; ni++)
            #pragma unroll
            for (int r = 0; r < 4; r++) acc[mi][ni][r] = 0.0f;

    auto stage_load = [&](int st, int kc) {
        const int tap = kc >> 2, cb = kc & 3;
        const int r = tap / 3, s = tap % 3;
        const float* As = g_wt + (size_t)(tap * CO + co_base) * CI + cb * 32;
        const float* Bs = xb + ((size_t)(n * 59 + h0 + r) * 64 + (s - 1)) * CI + cb * 32;
        float* dA = sA + st * TILEB;
        float* dB = sB + st * TILEB;
        #pragma unroll
        for (int i = 0; i < 4; i++) {
            int q = tid + 256 * i;
            int row = q >> 3, slot = q & 7;
            cp_async16(dA + row * SROW + slot * 4, As + row * CI + slot * 4);
            cp_async16(dB + row * SROW + slot * 4, Bs + row * CI + slot * 4);
        }
    };

    // prime pipeline
    stage_load(0, 0); CP_COMMIT();
    stage_load(1, 1); CP_COMMIT();

    for (int kc = 0; kc < 36; kc++) {
        CP_WAIT1();
        __syncthreads();

        const float* A = sA + (kc % STG) * TILEB;
        const float* B = sB + (kc % STG) * TILEB;
        #pragma unroll
        for (int kk = 0; kk < 4; kk++) {
            const int k0 = kk * 8;
            uint32_t af[2][4];
            #pragma unroll
            for (int mi = 0; mi < 2; mi++) {
                const float* Ab = A + (warp_m + mi * 16 + g) * SROW + k0 + t;
                af[mi][0] = __float_as_uint(Ab[0]);
                af[mi][1] = __float_as_uint(Ab[8 * SROW]);
                af[mi][2] = __float_as_uint(Ab[4]);
                af[mi][3] = __float_as_uint(Ab[8 * SROW + 4]);
            }
            #pragma unroll
            for (int ni = 0; ni < 8; ni++) {
                const float* Bb = B + (warp_n + ni * 8 + g) * SROW + k0 + t;
                uint32_t bf[2] = { __float_as_uint(Bb[0]), __float_as_uint(Bb[4]) };
                mma_tf32(acc[0][ni], af[0], bf);
                mma_tf32(acc[1][ni], af[1], bf);
            }
        }
        __syncthreads();

        const int nk = kc + STG - 1;
        if (nk < 36) stage_load(nk % STG, nk);
        CP_COMMIT();
    }

    // epilogue: c0/c1 = adjacent px -> float2 stores
    #pragma unroll
    for (int mi = 0; mi < 2; mi++)
        #pragma unroll
        for (int ni = 0; ni < 8; ni++)
            #pragma unroll
            for (int half = 0; half < 2; half++) {
                const int co = co_base + warp_m + mi * 16 + g + half * 8;
                const int px = warp_n + ni * 8 + 2 * t;
                const int hh = h0 + (px >> 6);
                const int w  = px & 63;
                if (w < 56) {
                    float2 v = make_float2(acc[mi][ni][half * 2], acc[mi][ni][half * 2 + 1]);
                    *(float2*)&out[(((size_t)n * CO + co) * HH + hh) * WW + w] = v;
                }
            }
}

// ---------------- host ----------------
extern "C" void kernel_launch(void* const* d_in, const int* in_sizes, int n_in,
                              void* d_out, int out_size)
{
    const float* x   = (const float*)d_in[0];
    const float* wgt = (const float*)d_in[1];
    float*       out = (float*)d_out;

    void* xt_ptr = nullptr;
    cudaGetSymbolAddress(&xt_ptr, g_xt);

    cudaMemsetAsync(xt_ptr, 0, sizeof(float) * (128 + (size_t)NNB * 59 * 64 * CI));
    xpose_kernel<<<dim3(4, HH, NNB), 256>>>(x);
    wxform_kernel<<<(9 * CO * CI + 255) / 256, 256>>>(wgt);

    cudaFuncSetAttribute(conv_mma_kernel, cudaFuncAttributeMaxDynamicSharedMemorySize, SMEM_BYTES);
    conv_mma_kernel<<<dim3(2, 28, NNB), 256, SMEM_BYTES>>>(out);
}

// round 4
// speedup vs baseline: 9.3362x; 2.0252x over previous
#include <cuda_runtime.h>
#include <cuda.h>
#include <cuda_fp16.h>
#include <cstdint>

#define NNB 32
#define CI  128
#define CO  256
#define HH  56
#define WW  56

// Padded NHWC x in fp16: [n][59 rows][64 cols][128 ci]; rows 1..56 = h 0..55,
// cols 0..55 = w, all padding zero. 128-half front guard for the (0,0,-1) read.
__device__ __align__(256) __half g_xt[128 + (size_t)NNB * 59 * 64 * CI];
__device__ __align__(256) __half g_wt[9 * CO * CI];   // [tap][co][ci]

// ---------------- helpers ----------------
__device__ __forceinline__ void cp_async16(uint32_t dst_smem, const void* src) {
    asm volatile("cp.async.cg.shared.global [%0], [%1], 16;" :: "r"(dst_smem), "l"(src) : "memory");
}
#define CP_COMMIT() asm volatile("cp.async.commit_group;" ::: "memory")
#define CP_WAIT1()  asm volatile("cp.async.wait_group 1;" ::: "memory")

#define LDM_X4(r0, r1, r2, r3, addr) \
    asm volatile("ldmatrix.sync.aligned.m8n8.x4.shared.b16 {%0,%1,%2,%3}, [%4];" \
        : "=r"(r0), "=r"(r1), "=r"(r2), "=r"(r3) : "r"(addr))

__device__ __forceinline__ void mma_f16(float d[4], const uint32_t a[4], uint32_t b0, uint32_t b1) {
    asm volatile(
        "mma.sync.aligned.m16n8k16.row.col.f32.f16.f16.f32 "
        "{%0,%1,%2,%3}, {%4,%5,%6,%7}, {%8,%9}, {%0,%1,%2,%3};"
        : "+f"(d[0]), "+f"(d[1]), "+f"(d[2]), "+f"(d[3])
        : "r"(a[0]), "r"(a[1]), "r"(a[2]), "r"(a[3]), "r"(b0), "r"(b1));
}

// ---------------- prologue ----------------
__global__ void xpose_kernel(const float* __restrict__ x) {
    __shared__ float s[32][57];
    const int cib = blockIdx.x;
    const int h   = blockIdx.y;
    const int n   = blockIdx.z;
    const int tid = threadIdx.x;
    for (int idx = tid; idx < 32 * WW; idx += 256) {
        int ci = idx / WW, w = idx % WW;
        s[ci][w] = x[(((size_t)n * CI + cib * 32 + ci) * HH + h) * WW + w];
    }
    __syncthreads();
    __half* xb = g_xt + 128;
    for (int idx = tid; idx < 32 * WW; idx += 256) {
        int w = idx / 32, ci = idx % 32;
        xb[((size_t)(n * 59 + h + 1) * 64 + w) * CI + cib * 32 + ci] = __float2half_rn(s[ci][w]);
    }
}

__global__ void wxform_kernel(const float* __restrict__ wgt) {
    int idx = blockIdx.x * 256 + threadIdx.x;
    if (idx >= 9 * CO * CI) return;
    int ci  = idx % CI;
    int t   = idx / CI;
    int co  = t % CO;
    int tap = t / CO;
    g_wt[idx] = __float2half_rn(wgt[((size_t)co * CI + ci) * 9 + tap]);
}

// ---------------- main kernel ----------------
// CTA: 128 co x 128 px (2 out rows x 64 padded w). K = 18 chunks of 64 ci.
// Stage: A 128x64 fp16 (16KB) + B 128x64 fp16 (16KB), XOR-swizzled 16B chunks.
constexpr int STG = 3;
constexpr int TILE_BYTES = 128 * 64 * 2;                  // 16384
constexpr int SMEM_BYTES = STG * 2 * TILE_BYTES;          // 98304

__global__ __launch_bounds__(256, 2)
void conv_mma_kernel(float* __restrict__ out)
{
    extern __shared__ char smem[];
    const uint32_t sm_u = (uint32_t)__cvta_generic_to_shared(smem);
    const uint32_t sA_u = sm_u;
    const uint32_t sB_u = sm_u + STG * TILE_BYTES;

    const int tid  = threadIdx.x;
    const int lane = tid & 31;
    const int warp = tid >> 5;
    const int g    = lane >> 2;
    const int t    = lane & 3;
    const int warp_m = (warp >> 1) * 32;   // 4 warps in m
    const int warp_n = (warp & 1) * 64;    // 2 warps in n

    const int co_base = blockIdx.x * 128;
    const int h0      = blockIdx.y * 2;
    const int n       = blockIdx.z;

    const __half* xb = g_xt + 128;

    // ldmatrix per-lane address components (row&7 == rowin everywhere)
    const int quad  = lane >> 3;
    const int rowin = lane & 7;
    const int qlow  = quad & 1;
    const int qhigh = quad >> 1;

    uint32_t aRowB[2], bRowB[4];
    #pragma unroll
    for (int mi = 0; mi < 2; mi++)
        aRowB[mi] = (uint32_t)(warp_m + mi * 16 + qlow * 8 + rowin) * 128u;
    #pragma unroll
    for (int p = 0; p < 4; p++)
        bRowB[p] = (uint32_t)(warp_n + (p * 2 + qhigh) * 8 + rowin) * 128u;

    float acc[2][8][4];
    #pragma unroll
    for (int mi = 0; mi < 2; mi++)
        #pragma unroll
        for (int ni = 0; ni < 8; ni++)
            #pragma unroll
            for (int r = 0; r < 4; r++) acc[mi][ni][r] = 0.0f;

    // cp.async mapping: 1024 chunks of 16B per operand per stage
    const int ld_row   = tid >> 3;       // +32 per iter
    const int ld_chunk = tid & 7;

    auto stage_load = [&](int st, int kc) {
        const int tap = kc >> 1, cihalf = kc & 1;
        const int r = tap / 3, s = tap % 3;
        const __half* As = g_wt + ((size_t)(tap * CO + co_base) * CI + cihalf * 64);
        const __half* Bs = xb + ((size_t)((n * 59 + h0 + r) * 64 + (s - 1)) * CI + cihalf * 64);
        const uint32_t dA = sA_u + st * TILE_BYTES;
        const uint32_t dB = sB_u + st * TILE_BYTES;
        #pragma unroll
        for (int i = 0; i < 4; i++) {
            const int row = ld_row + 32 * i;
            const uint32_t doff = (uint32_t)row * 128u + (uint32_t)(ld_chunk ^ (row & 7)) * 16u;
            const size_t soff = (size_t)row * CI + ld_chunk * 8;   // halves
            cp_async16(dA + doff, As + soff);
            cp_async16(dB + doff, Bs + soff);
        }
    };

    stage_load(0, 0); CP_COMMIT();
    stage_load(1, 1); CP_COMMIT();

    for (int kc = 0; kc < 18; kc++) {
        CP_WAIT1();
        __syncthreads();

        const uint32_t A = sA_u + (kc % STG) * TILE_BYTES;
        const uint32_t B = sB_u + (kc % STG) * TILE_BYTES;

        #pragma unroll
        for (int kk = 0; kk < 4; kk++) {
            uint32_t a[2][4];
            #pragma unroll
            for (int mi = 0; mi < 2; mi++) {
                const uint32_t addr = A + aRowB[mi] + (uint32_t)(((kk * 2 + qhigh) ^ rowin) * 16);
                LDM_X4(a[mi][0], a[mi][1], a[mi][2], a[mi][3], addr);
            }
            #pragma unroll
            for (int p = 0; p < 4; p++) {
                uint32_t b0, b1, b2, b3;
                const uint32_t addr = B + bRowB[p] + (uint32_t)(((kk * 2 + qlow) ^ rowin) * 16);
                LDM_X4(b0, b1, b2, b3, addr);
                mma_f16(acc[0][2 * p],     a[0], b0, b1);
                mma_f16(acc[1][2 * p],     a[1], b0, b1);
                mma_f16(acc[0][2 * p + 1], a[0], b2, b3);
                mma_f16(acc[1][2 * p + 1], a[1], b2, b3);
            }
        }
        __syncthreads();

        const int nk = kc + STG - 1;
        if (nk < 18) stage_load(nk % STG, nk);
        CP_COMMIT();
    }

    // epilogue: c0/c1 adjacent px -> float2 stores
    #pragma unroll
    for (int mi = 0; mi < 2; mi++)
        #pragma unroll
        for (int ni = 0; ni < 8; ni++)
            #pragma unroll
            for (int half = 0; half < 2; half++) {
                const int co = co_base + warp_m + mi * 16 + g + half * 8;
                const int px = warp_n + ni * 8 + 2 * t;
                const int hh = h0 + (px >> 6);
                const int w  = px & 63;
                if (w < 56) {
                    float2 v = make_float2(acc[mi][ni][half * 2], acc[mi][ni][half * 2 + 1]);
                    *(float2*)&out[(((size_t)n * CO + co) * HH + hh) * WW + w] = v;
                }
            }
}

// ---------------- host ----------------
extern "C" void kernel_launch(void* const* d_in, const int* in_sizes, int n_in,
                              void* d_out, int out_size)
{
    const float* x   = (const float*)d_in[0];
    const float* wgt = (const float*)d_in[1];
    float*       out = (float*)d_out;

    void* xt_ptr = nullptr;
    cudaGetSymbolAddress(&xt_ptr, g_xt);

    cudaMemsetAsync(xt_ptr, 0, sizeof(__half) * (128 + (size_t)NNB * 59 * 64 * CI));
    xpose_kernel<<<dim3(4, HH, NNB), 256>>>(x);
    wxform_kernel<<<(9 * CO * CI + 255) / 256, 256>>>(wgt);

    cudaFuncSetAttribute(conv_mma_kernel, cudaFuncAttributeMaxDynamicSharedMemorySize, SMEM_BYTES);
    conv_mma_kernel<<<dim3(2, 28, NNB), 256, SMEM_BYTES>>>(out);
}

// round 5
// speedup vs baseline: 11.9445x; 1.2794x over previous
#include <cuda_runtime.h>
#include <cuda.h>
#include <cuda_fp16.h>
#include <cstdint>

#define NNB 32
#define CI  128
#define CO  256
#define HH  56
#define WW  56

// Padded NHWC x in fp16: [n][59 rows][64 cols][128 ci]; rows 1..56 = h 0..55,
// cols 0..55 = w, all padding zero. 128-half front guard for the (h0=0, col -1) read.
__device__ __align__(256) __half g_xt[128 + (size_t)NNB * 59 * 64 * CI];
__device__ __align__(256) __half g_wt[9 * CO * CI];   // [tap][co][ci]

// ---------------- helpers ----------------
__device__ __forceinline__ void cp_async16(uint32_t dst_smem, const void* src) {
    asm volatile("cp.async.cg.shared.global [%0], [%1], 16;" :: "r"(dst_smem), "l"(src) : "memory");
}
#define CP_COMMIT() asm volatile("cp.async.commit_group;" ::: "memory")
#define CP_WAIT0()  asm volatile("cp.async.wait_group 0;" ::: "memory")

#define LDM_X4(r0, r1, r2, r3, addr) \
    asm volatile("ldmatrix.sync.aligned.m8n8.x4.shared.b16 {%0,%1,%2,%3}, [%4];" \
        : "=r"(r0), "=r"(r1), "=r"(r2), "=r"(r3) : "r"(addr))

__device__ __forceinline__ void mma_f16(float d[4], const uint32_t a[4], uint32_t b0, uint32_t b1) {
    asm volatile(
        "mma.sync.aligned.m16n8k16.row.col.f32.f16.f16.f32 "
        "{%0,%1,%2,%3}, {%4,%5,%6,%7}, {%8,%9}, {%0,%1,%2,%3};"
        : "+f"(d[0]), "+f"(d[1]), "+f"(d[2]), "+f"(d[3])
        : "r"(a[0]), "r"(a[1]), "r"(a[2]), "r"(a[3]), "r"(b0), "r"(b1));
}

// ---------------- prologue ----------------
// One block per (padded row h_p, n). Writes the FULL 64x128-half padded row
// (zeros included) with 16B stores; eliminates the big memset.
__global__ __launch_bounds__(256)
void xpose_kernel(const float* __restrict__ x) {
    __shared__ float s[128][57];
    const int h_p = blockIdx.x;     // 0..58
    const int n   = blockIdx.y;
    const int tid = threadIdx.x;
    const int h   = h_p - 1;
    const bool valid = (h >= 0) && (h < HH);

    if (valid) {
        for (int idx = tid; idx < CI * WW; idx += 256) {
            int ci = idx / WW, w = idx % WW;
            s[ci][w] = x[(((size_t)n * CI + ci) * HH + h) * WW + w];
        }
    }
    __syncthreads();

    __half* dst = g_xt + 128 + (size_t)(n * 59 + h_p) * 64 * CI;
    for (int idx = tid; idx < 64 * 16; idx += 256) {
        const int w = idx >> 4;         // 0..63
        const int g = idx & 15;         // ci group of 8
        uint4 v = make_uint4(0u, 0u, 0u, 0u);
        if (valid && w < WW) {
            __half2 p0 = __floats2half2_rn(s[g * 8 + 0][w], s[g * 8 + 1][w]);
            __half2 p1 = __floats2half2_rn(s[g * 8 + 2][w], s[g * 8 + 3][w]);
            __half2 p2 = __floats2half2_rn(s[g * 8 + 4][w], s[g * 8 + 5][w]);
            __half2 p3 = __floats2half2_rn(s[g * 8 + 6][w], s[g * 8 + 7][w]);
            v.x = *(uint32_t*)&p0; v.y = *(uint32_t*)&p1;
            v.z = *(uint32_t*)&p2; v.w = *(uint32_t*)&p3;
        }
        *(uint4*)(dst + (size_t)w * CI + g * 8) = v;
    }
}

__global__ void wxform_kernel(const float* __restrict__ wgt) {
    int idx = blockIdx.x * 256 + threadIdx.x;
    if (idx >= 9 * CO * CI) return;
    int ci  = idx % CI;
    int t   = idx / CI;
    int co  = t % CO;
    int tap = t / CO;
    g_wt[idx] = __float2half_rn(wgt[((size_t)co * CI + ci) * 9 + tap]);
}

// ---------------- main kernel ----------------
// CTA: 128 co x 128 px (2 out rows x 64 padded w).
// B: resident 258-row x 64ci x 2 halves window (66KB), loaded ONCE.
//    Tap (r,s) = row offset r*64+s into the window.
// A: 18 chunks (tap x ci-half, 16KB each), 2-slot cp.async pipeline,
//    prefetch issued mid-compute, ONE syncthreads per chunk.
constexpr int B_HALF_BYTES = 258 * 128;              // 33024
constexpr int B_BYTES      = 2 * B_HALF_BYTES;       // 66048
constexpr int A_TILE       = 128 * 64 * 2;           // 16384
constexpr int SMEM_BYTES   = B_BYTES + 2 * A_TILE;   // 98816

__global__ __launch_bounds__(256, 2)
void conv_mma_kernel(float* __restrict__ out)
{
    extern __shared__ char smem[];
    const uint32_t sm_u = (uint32_t)__cvta_generic_to_shared(smem);
    const uint32_t B_u  = sm_u;
    const uint32_t A_u  = sm_u + B_BYTES;

    const int tid  = threadIdx.x;
    const int lane = tid & 31;
    const int warp = tid >> 5;
    const int g    = lane >> 2;
    const int t    = lane & 3;
    const int warp_m = (warp >> 1) * 32;   // 4 warps in m
    const int warp_n = (warp & 1) * 64;    // 2 warps in n

    const int co_base = blockIdx.x * 128;
    const int h0      = blockIdx.y * 2;
    const int n       = blockIdx.z;

    const __half* xb = g_xt + 128;

    const int quad  = lane >> 3;
    const int rowin = lane & 7;
    const int qlow  = quad & 1;
    const int qhigh = quad >> 1;

    uint32_t aRowB[2];
    #pragma unroll
    for (int mi = 0; mi < 2; mi++)
        aRowB[mi] = (uint32_t)(warp_m + mi * 16 + qlow * 8 + rowin) * 128u;

    float acc[2][8][4];
    #pragma unroll
    for (int mi = 0; mi < 2; mi++)
        #pragma unroll
        for (int ni = 0; ni < 8; ni++)
            #pragma unroll
            for (int r = 0; r < 4; r++) acc[mi][ni][r] = 0.0f;

    // ---- B preload: contiguous 258-row slice starting at flat row (n*59+h0)*64 - 1
    {
        const long long F0 = ((long long)(n * 59 + h0) * 64 - 1) * CI;  // halves
        #pragma unroll
        for (int half = 0; half < 2; half++) {
            const __half* src = xb + F0 + half * 64;
            const uint32_t dstb = B_u + half * B_HALF_BYTES;
            for (int idx = tid; idx < 258 * 8; idx += 256) {
                const int i = idx >> 3, c = idx & 7;
                cp_async16(dstb + (uint32_t)i * 128u + (uint32_t)((c ^ (i & 7)) * 16),
                           src + (size_t)i * CI + c * 8);
            }
        }
    }

    // ---- A chunk loader (tap = kc>>1, ci-half = kc&1) into slot kc&1
    auto loadA = [&](int kc) {
        const int tap = kc >> 1, cihalf = kc & 1;
        const __half* src = g_wt + (size_t)(tap * CO + co_base) * CI + cihalf * 64;
        const uint32_t dA = A_u + (kc & 1) * A_TILE;
        #pragma unroll
        for (int i = 0; i < 4; i++) {
            const int q = tid + 256 * i;
            const int row = q >> 3, c = q & 7;
            cp_async16(dA + (uint32_t)row * 128u + (uint32_t)((c ^ (row & 7)) * 16),
                       src + (size_t)row * CI + c * 8);
        }
    };

    loadA(0);
    CP_COMMIT();

    #pragma unroll
    for (int kc = 0; kc < 18; kc++) {
        const int tap = kc >> 1, cihalf = kc & 1;
        const int r = tap / 3, s = tap % 3;
        const int off = r * 64 + s;           // tap row offset into B window

        CP_WAIT0();
        __syncthreads();

        const uint32_t A  = A_u + (kc & 1) * A_TILE;
        const uint32_t Bb = B_u + cihalf * B_HALF_BYTES;
        const int ro = (rowin + off) & 7;

        uint32_t bBase[4];
        #pragma unroll
        for (int p = 0; p < 4; p++)
            bBase[p] = Bb + (uint32_t)(warp_n + (p * 2 + qhigh) * 8 + rowin + off) * 128u;

        #pragma unroll
        for (int kk = 0; kk < 4; kk++) {
            uint32_t a[2][4];
            #pragma unroll
            for (int mi = 0; mi < 2; mi++)
                LDM_X4(a[mi][0], a[mi][1], a[mi][2], a[mi][3],
                       A + aRowB[mi] + (uint32_t)(((kk * 2 + qhigh) ^ rowin) * 16));
            #pragma unroll
            for (int p = 0; p < 4; p++) {
                uint32_t b0, b1, b2, b3;
                LDM_X4(b0, b1, b2, b3,
                       bBase[p] + (uint32_t)(((kk * 2 + qlow) ^ ro) * 16));
                mma_f16(acc[0][2 * p],     a[0], b0, b1);
                mma_f16(acc[1][2 * p],     a[1], b0, b1);
                mma_f16(acc[0][2 * p + 1], a[0], b2, b3);
                mma_f16(acc[1][2 * p + 1], a[1], b2, b3);
            }
            if (kk == 1) {                      // prefetch next A mid-compute
                if (kc + 1 < 18) loadA(kc + 1); // slot (kc+1)&1 freed at kc-1,
                CP_COMMIT();                    // guarded by this chunk's sync
            }
        }
    }

    // ---- epilogue: c0/c1 adjacent px -> float2 stores
    #pragma unroll
    for (int mi = 0; mi < 2; mi++)
        #pragma unroll
        for (int ni = 0; ni < 8; ni++)
            #pragma unroll
            for (int half = 0; half < 2; half++) {
                const int co = co_base + warp_m + mi * 16 + g + half * 8;
                const int px = warp_n + ni * 8 + 2 * t;
                const int hh = h0 + (px >> 6);
                const int w  = px & 63;
                if (w < 56) {
                    float2 v = make_float2(acc[mi][ni][half * 2], acc[mi][ni][half * 2 + 1]);
                    *(float2*)&out[(((size_t)n * CO + co) * HH + hh) * WW + w] = v;
                }
            }
}

// ---------------- host ----------------
extern "C" void kernel_launch(void* const* d_in, const int* in_sizes, int n_in,
                              void* d_out, int out_size)
{
    const float* x   = (const float*)d_in[0];
    const float* wgt = (const float*)d_in[1];
    float*       out = (float*)d_out;

    void* xt_ptr = nullptr;
    cudaGetSymbolAddress(&xt_ptr, g_xt);

    cudaMemsetAsync(xt_ptr, 0, 256);   // front guard row only
    xpose_kernel<<<dim3(59, NNB), 256>>>(x);
    wxform_kernel<<<(9 * CO * CI + 255) / 256, 256>>>(wgt);

    cudaFuncSetAttribute(conv_mma_kernel, cudaFuncAttributeMaxDynamicSharedMemorySize, SMEM_BYTES);
    conv_mma_kernel<<<dim3(2, 28, NNB), 256, SMEM_BYTES>>>(out);
}